// round 14
// baseline (speedup 1.0000x reference)
#include <cuda_runtime.h>
#include <cuda_bf16.h>
#include <cstdint>

// FCGAT == relu(x @ W_w^T + W_b)  (softmax over j sums to 1 vs 'nkj,nkd->nkd').
// GEMM M=32768 N=256 K=256 fp32 via 3-term bf16 split on mma.sync (HMMA).
// X staged fp32 via 2-deep cp.async ring; split reads smem. The cp.async
// consume pattern is wait_group -> __syncthreads -> read (cross-thread data).

#define M_TOT   32768
#define NDIM    256
#define KDIM    256
#define BM      128
#define BN      128
#define KC      32
#define NCHUNK  8

#define ROWB    80                  // 64B bf16 row + 16B pad
#define PLANE   10240               // 128 * ROWB
#define ABUF(b) ((b) * 20480)                // hi plane; lo at +PLANE
#define BBUF(b) (40960 + (b) * 20480)        // hi plane; lo at +PLANE
#define XBUF(b) (81920 + (b) * 16384)        // fp32 staging, piece-interleaved
#define SMEM_TOTAL 114688                    // 112 KB -> 2 CTAs/SM

#define X_ELEMS  8388608
#define WW_ELEMS 65536
#define WB_ELEMS 256

__device__ __align__(16) unsigned short g_Whi[NDIM * KDIM];
__device__ __align__(16) unsigned short g_Wlo[NDIM * KDIM];

__global__ void wsplit_kernel(const float* __restrict__ W) {
    int i = blockIdx.x * 256 + threadIdx.x;
    float f = W[i];
    __nv_bfloat16 hb = __float2bfloat16(f);
    __nv_bfloat16 lb = __float2bfloat16(f - __bfloat162float(hb));
    g_Whi[i] = reinterpret_cast<unsigned short&>(hb);
    g_Wlo[i] = reinterpret_cast<unsigned short&>(lb);
}

// ---------------- helpers ----------------
__device__ __forceinline__ uint32_t smem_u32(const void* p) {
    uint32_t a;
    asm("{ .reg .u64 t; cvta.to.shared.u64 t, %1; cvt.u32.u64 %0, t; }"
        : "=r"(a) : "l"(p));
    return a;
}
__device__ __forceinline__ void ldsm4(uint32_t* r, uint32_t addr) {
    asm volatile("ldmatrix.sync.aligned.m8n8.x4.shared.b16 {%0,%1,%2,%3}, [%4];"
                 : "=r"(r[0]), "=r"(r[1]), "=r"(r[2]), "=r"(r[3]) : "r"(addr));
}
__device__ __forceinline__ void mma_bf16(float* c, const uint32_t* a,
                                         const uint32_t* b) {
    asm("mma.sync.aligned.m16n8k16.row.col.f32.bf16.bf16.f32 "
        "{%0,%1,%2,%3},{%4,%5,%6,%7},{%8,%9},{%0,%1,%2,%3};"
        : "+f"(c[0]), "+f"(c[1]), "+f"(c[2]), "+f"(c[3])
        : "r"(a[0]), "r"(a[1]), "r"(a[2]), "r"(a[3]), "r"(b[0]), "r"(b[1]));
}
__device__ __forceinline__ void cpasync16(uint32_t dst, const void* src) {
    asm volatile("cp.async.cg.shared.global [%0], [%1], 16;"
                 :: "r"(dst), "l"(src) : "memory");
}
#define CP_COMMIT() asm volatile("cp.async.commit_group;" ::: "memory")
#define STS128(a, r0, r1, r2, r3) \
    asm volatile("st.shared.v4.b32 [%0], {%1,%2,%3,%4};" \
                 :: "r"(a), "r"(r0), "r"(r1), "r"(r2), "r"(r3) : "memory")
#define LDS128F(f0, f1, f2, f3, a) \
    asm volatile("ld.shared.v4.f32 {%0,%1,%2,%3}, [%4];" \
                 : "=f"(f0), "=f"(f1), "=f"(f2), "=f"(f3) : "r"(a))

// cp.async fp32 X chunk j -> xbuf. Piece p (16B) of the 128x32 chunk lives at
// (p&7)*2048 + (p>>3)*16, p = row*8 + colgroup... concretely addr(row,g) =
// g*2048 + row*16 (g = col/4). Global side: 8 lanes cover one 128B row-chunk.
__device__ __forceinline__ void stage_x(const float* __restrict__ Xblk, int j,
                                        uint32_t xb, int tid) {
    const int sub = tid & 7, rr = tid >> 3;
    const float* src = Xblk + (size_t)rr * KDIM + j * KC + sub * 4;
    uint32_t dst = xb + sub * 2048 + rr * 16;
#pragma unroll
    for (int i = 0; i < 4; i++)
        cpasync16(dst + i * 512, src + (size_t)32 * i * KDIM);
}

// Convert staged fp32 chunk -> bf16 hi/lo planes of A buffer.
// Reads CROSS-THREAD cp.async data: caller must wait_group + __syncthreads first.
__device__ __forceinline__ void convert_x(uint32_t xb, uint32_t aDst) {
    float f[16];
#pragma unroll
    for (int k = 0; k < 4; k++)
        LDS128F(f[4 * k], f[4 * k + 1], f[4 * k + 2], f[4 * k + 3],
                xb + k * 2048);
    uint32_t h[8], l[8];
#pragma unroll
    for (int j = 0; j < 8; j++) {
        float a = f[2 * j], b = f[2 * j + 1];
        uint32_t hp;
        asm("cvt.rn.bf16x2.f32 %0, %1, %2;" : "=r"(hp) : "f"(b), "f"(a));
        float ha = __uint_as_float(hp << 16);
        float hb = __uint_as_float(hp & 0xFFFF0000u);
        uint32_t lp;
        asm("cvt.rn.bf16x2.f32 %0, %1, %2;" : "=r"(lp) : "f"(b - hb), "f"(a - ha));
        h[j] = hp; l[j] = lp;
    }
    STS128(aDst,              h[0], h[1], h[2], h[3]);
    STS128(aDst + 16,         h[4], h[5], h[6], h[7]);
    STS128(aDst + PLANE,      l[0], l[1], l[2], l[3]);
    STS128(aDst + PLANE + 16, l[4], l[5], l[6], l[7]);
}

// cp.async pre-split W chunk (hi+lo).
__device__ __forceinline__ void load_w(int c, uint32_t dstHi, int row, int half,
                                       int n0) {
    const unsigned short* sh = &g_Whi[(size_t)(n0 + row) * KDIM + c * KC + half * 16];
    const unsigned short* sl = &g_Wlo[(size_t)(n0 + row) * KDIM + c * KC + half * 16];
    cpasync16(dstHi,              sh);
    cpasync16(dstHi + 16,         sh + 8);
    cpasync16(dstHi + PLANE,      sl);
    cpasync16(dstHi + PLANE + 16, sl + 8);
}

// =========================== main kernel ===========================
__global__ __launch_bounds__(256, 2)
void fcgat_mma(const float* __restrict__ X,
               const float* __restrict__ bias,
               float* __restrict__ out)
{
    extern __shared__ __align__(1024) char smem[];
    const uint32_t sb = smem_u32(smem);
    const int tid  = threadIdx.x;
    const int lane = tid & 31;
    const int wid  = tid >> 5;
    const int warp_m = wid & 1;
    const int warp_n = wid >> 1;

    const int row  = tid & 127;
    const int half = tid >> 7;
    const int n0 = blockIdx.x * BN;
    const float* Xblk = X + (size_t)blockIdx.y * BM * KDIM;

    const uint32_t aDstR = sb + row * ROWB + half * 32;       // + ABUF(b)
    const uint32_t xRdR  = sb + half * 8192 + row * 16;       // + XBUF(b)
    const uint32_t bDstR = sb + row * ROWB + half * 32;       // + BBUF(b)

    const int i4 = lane >> 3;
    const uint32_t aBase = sb + (warp_m * 64 + (i4 & 1) * 8 + (lane & 7)) * ROWB
                              + (i4 >> 1) * 16;
    const uint32_t bBase = sb + 40960
                              + (warp_n * 32 + (i4 >> 1) * 8 + (lane & 7)) * ROWB
                              + (i4 & 1) * 16;

    float acc[4][4][4];
#pragma unroll
    for (int a = 0; a < 4; a++)
#pragma unroll
        for (int b = 0; b < 4; b++)
#pragma unroll
            for (int d = 0; d < 4; d++) acc[a][b][d] = 0.0f;

    // ---- prologue: W(0); X(0); X(1) as three groups ----
    load_w(0, bDstR + BBUF(0) - 40960 + 40960, row, half, n0);  // = sb+BBUF(0)+...
    CP_COMMIT();
    stage_x(Xblk, 0, sb + XBUF(0), tid);
    CP_COMMIT();
    stage_x(Xblk, 1, sb + XBUF(1), tid);
    CP_COMMIT();
    asm volatile("cp.async.wait_group 1;" ::: "memory");  // own W0, X0 done
    __syncthreads();                                      // ALL threads' W0/X0 visible
    convert_x(xRdR + XBUF(0), aDstR + ABUF(0));
    // ABUF(0) STS becomes visible at the first mid-iteration barrier below.

#pragma unroll
    for (int c = 0; c < NCHUNK; c++) {
        const uint32_t buf  = c & 1;
        const uint32_t nbuf = buf ^ 1;

        if (c + 1 < NCHUNK) {
            load_w(c + 1, sb + BBUF(nbuf) + row * ROWB + half * 32,
                   row, half, n0);
            CP_COMMIT();
        }
        if (c + 2 < NCHUNK) {
            stage_x(Xblk, c + 2, sb + XBUF(buf), tid);
            CP_COMMIT();
        }

        // Drain X(c+1): after commits, in-flight = {X(c+1), W(c+1), X(c+2)}.
        // wait_group leaves W(c+1) [+X(c+2)] pending. Then barrier so OTHER
        // threads' X(c+1) pieces are visible, then convert. This barrier also
        // publishes the previous convert's STS (incl. prologue) before MMA.
        if (c + 1 < NCHUNK) {
            if (c + 2 < NCHUNK)
                asm volatile("cp.async.wait_group 2;" ::: "memory");
            else
                asm volatile("cp.async.wait_group 1;" ::: "memory");
            __syncthreads();
            convert_x(xRdR + XBUF(nbuf), aDstR + ABUF(nbuf));
        } else {
            __syncthreads();
        }

        // ---- MMA on chunk c ----
#pragma unroll
        for (int ks = 0; ks < 2; ks++) {
            const uint32_t ao = aBase + buf * 20480 + ks * 32;
            const uint32_t bo = bBase + buf * 20480 + ks * 32;
            uint32_t ah[16], bh[8], bl[8];
            ldsm4(bh + 0, bo);
            ldsm4(bh + 4, bo + 1280);
            ldsm4(bl + 0, bo + PLANE);
            ldsm4(bl + 4, bo + PLANE + 1280);
#pragma unroll
            for (int tm = 0; tm < 4; tm++) ldsm4(ah + tm * 4, ao + tm * 1280);
#pragma unroll
            for (int tm = 0; tm < 4; tm++)
#pragma unroll
                for (int tn = 0; tn < 4; tn++)
                    mma_bf16(acc[tm][tn], ah + tm * 4, bh + tn * 2);  // hi*hi
#pragma unroll
            for (int tm = 0; tm < 4; tm++)
#pragma unroll
                for (int tn = 0; tn < 4; tn++)
                    mma_bf16(acc[tm][tn], ah + tm * 4, bl + tn * 2);  // hi*lo
#pragma unroll
            for (int tm = 0; tm < 4; tm++)
                ldsm4(ah + tm * 4, ao + PLANE + tm * 1280);
#pragma unroll
            for (int tm = 0; tm < 4; tm++)
#pragma unroll
                for (int tn = 0; tn < 4; tn++)
                    mma_bf16(acc[tm][tn], ah + tm * 4, bh + tn * 2);  // lo*hi
        }

        // Drain W(c+1) (keep X(c+2) in flight); end barrier publishes BBUF(nbuf)
        // and this iteration's convert STS for the next MMA.
        if (c + 1 < NCHUNK) {
            if (c + 2 < NCHUNK)
                asm volatile("cp.async.wait_group 1;" ::: "memory");
            else
                asm volatile("cp.async.wait_group 0;" ::: "memory");
        }
        __syncthreads();
    }

    // ---- epilogue: bias + relu straight from fragments ----
    const int m0 = blockIdx.y * BM + warp_m * 64 + (lane >> 2);
    const int colBase = n0 + warp_n * 32 + (lane & 3) * 2;
#pragma unroll
    for (int tn = 0; tn < 4; tn++) {
        const int col = colBase + tn * 8;
        const float2 bv = *reinterpret_cast<const float2*>(&bias[col]);
#pragma unroll
        for (int tm = 0; tm < 4; tm++) {
            const int r = m0 + tm * 16;
            float2 o0, o1;
            o0.x = fmaxf(acc[tm][tn][0] + bv.x, 0.0f);
            o0.y = fmaxf(acc[tm][tn][1] + bv.y, 0.0f);
            o1.x = fmaxf(acc[tm][tn][2] + bv.x, 0.0f);
            o1.y = fmaxf(acc[tm][tn][3] + bv.y, 0.0f);
            *reinterpret_cast<float2*>(&out[(size_t)r * NDIM + col])       = o0;
            *reinterpret_cast<float2*>(&out[(size_t)(r + 8) * NDIM + col]) = o1;
        }
    }
}

extern "C" void kernel_launch(void* const* d_in, const int* in_sizes, int n_in,
                              void* d_out, int out_size)
{
    const float* x  = (n_in > 0) ? (const float*)d_in[0] : nullptr;
    const float* Ww = (n_in > 1) ? (const float*)d_in[1] : nullptr;
    const float* Wb = (n_in > 2) ? (const float*)d_in[2] : nullptr;
    for (int i = 0; i < n_in; i++) {
        if (in_sizes[i] == X_ELEMS)       x  = (const float*)d_in[i];
        else if (in_sizes[i] == WW_ELEMS) Ww = (const float*)d_in[i];
        else if (in_sizes[i] == WB_ELEMS) Wb = (const float*)d_in[i];
    }

    wsplit_kernel<<<256, 256>>>(Ww);

    static bool attr_set = false;
    if (!attr_set) {
        cudaFuncSetAttribute(fcgat_mma,
                             cudaFuncAttributeMaxDynamicSharedMemorySize,
                             SMEM_TOTAL);
        attr_set = true;
    }
    dim3 grid(NDIM / BN, M_TOT / BM);   // (2, 256)
    fcgat_mma<<<grid, 256, SMEM_TOTAL>>>(x, Wb, (float*)d_out);
}